// round 14
// baseline (speedup 1.0000x reference)
#include <cuda_runtime.h>
#include <cuda_fp16.h>

#define RR 128
#define BASIS 9
#define DATA_DIM 28
#define NUM_STEPS 256
#define STEP_SIZE 0.001f
#define BG 1.0f

#define NVOX (RR*RR*RR)           // 2097152
// 32 halves per voxel, interleaved for HFMA2 (R6 layout):
//  halves 0..17 : (c0_j, c1_j) pairs, j = 0..8
//  halves 18..26: c2_0 .. c2_8
//  half  27     : 0
//  half  28     : sigma
//  halves 29..31: 0
__device__ __align__(64) uint4 g_grid[NVOX * 4];   // 128 MiB, 64B records

// 256-bit load (Blackwell): one LDG.E.256 pulls 32B per lane.
__device__ __forceinline__ void ldg256(const uint4* p, uint4& a, uint4& b)
{
    asm volatile("ld.global.nc.v8.b32 {%0,%1,%2,%3,%4,%5,%6,%7}, [%8];"
        : "=r"(a.x), "=r"(a.y), "=r"(a.z), "=r"(a.w),
          "=r"(b.x), "=r"(b.y), "=r"(b.z), "=r"(b.w)
        : "l"(p));
}

// ---------------------------------------------------------------------------
// Conversion via smem staging (R10 version)
// ---------------------------------------------------------------------------
__global__ void __launch_bounds__(256)
convert_kernel(const float* __restrict__ tree)
{
    __shared__ float sm[64 * DATA_DIM];
    int tid = threadIdx.x;
    long long v0 = (long long)blockIdx.x * 64;

    const float4* src4 = reinterpret_cast<const float4*>(tree) + v0 * 7;
    float4* sm4 = reinterpret_cast<float4*>(sm);
    #pragma unroll
    for (int k = tid; k < 448; k += 256)
        sm4[k] = __ldg(src4 + k);
    __syncthreads();

    int vl = tid >> 2;
    int q  = tid & 3;
    const float* f = sm + vl * DATA_DIM;

    __half h[8];
    if (q == 0) {
        h[0]=__float2half_rn(f[0]);  h[1]=__float2half_rn(f[9]);
        h[2]=__float2half_rn(f[1]);  h[3]=__float2half_rn(f[10]);
        h[4]=__float2half_rn(f[2]);  h[5]=__float2half_rn(f[11]);
        h[6]=__float2half_rn(f[3]);  h[7]=__float2half_rn(f[12]);
    } else if (q == 1) {
        h[0]=__float2half_rn(f[4]);  h[1]=__float2half_rn(f[13]);
        h[2]=__float2half_rn(f[5]);  h[3]=__float2half_rn(f[14]);
        h[4]=__float2half_rn(f[6]);  h[5]=__float2half_rn(f[15]);
        h[6]=__float2half_rn(f[7]);  h[7]=__float2half_rn(f[16]);
    } else if (q == 2) {
        h[0]=__float2half_rn(f[8]);  h[1]=__float2half_rn(f[17]);
        h[2]=__float2half_rn(f[18]); h[3]=__float2half_rn(f[19]);
        h[4]=__float2half_rn(f[20]); h[5]=__float2half_rn(f[21]);
        h[6]=__float2half_rn(f[22]); h[7]=__float2half_rn(f[23]);
    } else {
        h[0]=__float2half_rn(f[24]); h[1]=__float2half_rn(f[25]);
        h[2]=__float2half_rn(f[26]); h[3]=__float2half_rn(0.0f);
        h[4]=__float2half_rn(f[27]); h[5]=__float2half_rn(0.0f);
        h[6]=__float2half_rn(0.0f);  h[7]=__float2half_rn(0.0f);
    }
    g_grid[v0 * 4 + tid] = *reinterpret_cast<uint4*>(h);
}

// ---------------------------------------------------------------------------
// Main renderer: R12 structure, SH tables parked in smem to raise occupancy.
// ---------------------------------------------------------------------------
__global__ void __launch_bounds__(128, 10)
volrend_kernel(const float* __restrict__ origins,
               const float* __restrict__ dirs,
               const float* __restrict__ viewdirs,
               const float* __restrict__ invradius,
               float* __restrict__ out,
               int nb)
{
    // Per-thread coefficient slots: [entry*128 + tid], no cross-thread sharing.
    // entries 0..8  = s01[j] ; entries 9..13 = s2[k]
    __shared__ __half2 sm_tab[14 * 128];
    #define S01(j) sm_tab[(j)*128 + threadIdx.x]
    #define S2(k)  sm_tab[(9+(k))*128 + threadIdx.x]

    int i = blockIdx.x * blockDim.x + threadIdx.x;
    if (i >= nb) return;

    float ox = origins[3*i+0], oy = origins[3*i+1], oz = origins[3*i+2];
    float dx = dirs[3*i+0],    dy = dirs[3*i+1],    dz = dirs[3*i+2];
    float inv_norm = rsqrtf(dx*dx + dy*dy + dz*dz);
    dx *= inv_norm; dy *= inv_norm; dz *= inv_norm;

    {
        float vx = viewdirs[3*i+0], vy = viewdirs[3*i+1], vz = viewdirs[3*i+2];
        float sh[BASIS];
        sh[0] =  0.28209479177387814f;
        sh[1] = -0.4886025119029199f * vy;
        sh[2] =  0.4886025119029199f * vz;
        sh[3] = -0.4886025119029199f * vx;
        sh[4] =  1.0925484305920792f * vx * vy;
        sh[5] = -1.0925484305920792f * vy * vz;
        sh[6] =  0.31539156525252005f * (2.0f*vz*vz - vx*vx - vy*vy);
        sh[7] = -1.0925484305920792f * vx * vz;
        sh[8] =  0.5462742152960396f * (vx*vx - vy*vy);

        #pragma unroll
        for (int j = 0; j < BASIS; ++j) S01(j) = __floats2half2_rn(sh[j], sh[j]);
        S2(0) = __floats2half2_rn(sh[0], sh[1]);
        S2(1) = __floats2half2_rn(sh[2], sh[3]);
        S2(2) = __floats2half2_rn(sh[4], sh[5]);
        S2(3) = __floats2half2_rn(sh[6], sh[7]);
        S2(4) = __floats2half2_rn(sh[8], 0.0f);
    }

    float idrx = 1.0f / (dx + 1e-9f);
    float idry = 1.0f / (dy + 1e-9f);
    float idrz = 1.0f / (dz + 1e-9f);

    float t1x = -ox * idrx, t2x = t1x + idrx;
    float t1y = -oy * idry, t2y = t1y + idry;
    float t1z = -oz * idrz, t2z = t1z + idrz;
    float tmin = fmaxf(fmaxf(fminf(t1x,t2x), fminf(t1y,t2y)), fminf(t1z,t2z));
    tmin = fmaxf(tmin, 0.0f);
    float tmax = fminf(fminf(fmaxf(t1x,t2x), fmaxf(t1y,t2y)), fmaxf(t1z,t2z));
    tmax = fminf(tmax, 1e9f);

    float irx = invradius[0], iry = invradius[1], irz = invradius[2];
    float dsx = dx / irx, dsy = dy / iry, dsz = dz / irz;
    float delta_scale = sqrtf(dsx*dsx + dsy*dsy + dsz*dsz);

    float oxR = ox * (float)RR, oyR = oy * (float)RR, ozR = oz * (float)RR;
    float dxR = dx * (float)RR, dyR = dy * (float)RR, dzR = dz * (float)RR;

    float t = tmin;
    float light = 1.0f;
    float out0 = 0.0f, out1 = 0.0f, out2 = 0.0f;
    const float cube_sz = 1.0f / (float)RR;

    #define GEOM(tt, dt_o, vp_o)                                               \
    {                                                                          \
        float px = fmaf((tt), dxR, oxR);                                       \
        float py = fmaf((tt), dyR, oyR);                                       \
        float pz = fmaf((tt), dzR, ozR);                                       \
        float fx = fminf(fmaxf(floorf(px), 0.0f), (float)(RR-1));              \
        float fy = fminf(fmaxf(floorf(py), 0.0f), (float)(RR-1));              \
        float fz = fminf(fmaxf(floorf(pz), 0.0f), (float)(RR-1));              \
        int flat = (int)fmaf(fx, 16384.0f, fmaf(fy, 128.0f, fz));              \
        (vp_o) = g_grid + (size_t)flat * 4;                                    \
        float cx = px - fx, cy = py - fy, cz = pz - fz;                        \
        float u1x = -cx * idrx, u2x = u1x + idrx;                              \
        float u1y = -cy * idry, u2y = u1y + idry;                              \
        float u1z = -cz * idrz, u2z = u1z + idrz;                              \
        float s0 = fmaxf(fmaxf(fminf(u1x,u2x), fminf(u1y,u2y)), fminf(u1z,u2z)); \
        s0 = fmaxf(s0, 0.0f);                                                  \
        float s1 = fminf(fminf(fmaxf(u1x,u2x), fmaxf(u1y,u2y)), fmaxf(u1z,u2z)); \
        s1 = fminf(s1, 1e9f);                                                  \
        (dt_o) = (s1 - s0) * cube_sz + STEP_SIZE;                              \
    }

    if (tmin < tmax) {
        float dt_cur;
        const uint4* vp;
        GEOM(t, dt_cur, vp);
        uint4 b0, b1, b2, b3;
        ldg256(vp,     b0, b1);
        ldg256(vp + 2, b2, b3);

        #pragma unroll 1
        for (int s = 0; s < NUM_STEPS; ++s) {
            uint4 a0 = b0, a1 = b1, a2 = b2, a3 = b3;
            float dt = dt_cur;

            // Prefetch next step before shading
            float t_new = t + dt;
            bool more = (t_new < tmax) && (s + 1 < NUM_STEPS);
            float dt_next = 0.0f;
            if (more) {
                const uint4* vpn;
                GEOM(t_new, dt_next, vpn);
                ldg256(vpn,     b0, b1);
                ldg256(vpn + 2, b2, b3);
            }

            // Shade: half2 SIMD dot products, coefficients from smem
            __half2 v[16];
            *reinterpret_cast<uint4*>(v +  0) = a0;
            *reinterpret_cast<uint4*>(v +  4) = a1;
            *reinterpret_cast<uint4*>(v +  8) = a2;
            *reinterpret_cast<uint4*>(v + 12) = a3;

            __half2 acc01 = __hmul2(S01(0), v[0]);
            #pragma unroll
            for (int j = 1; j < BASIS; ++j)
                acc01 = __hfma2(S01(j), v[j], acc01);
            __half2 acc2 = __hmul2(S2(0), v[9]);
            #pragma unroll
            for (int k = 1; k < 5; ++k)
                acc2 = __hfma2(S2(k), v[9 + k], acc2);

            float2 c01 = __half22float2(acc01);
            float2 c2p = __half22float2(acc2);
            float c2 = c2p.x + c2p.y;

            float sigma = fmaxf(__half2float(__low2half(v[14])), 0.0f);
            float att = __expf(-dt * sigma * delta_scale);
            float weight = light * (1.0f - att);

            float r0 = __fdividef(1.0f, 1.0f + __expf(-c01.x));
            float r1 = __fdividef(1.0f, 1.0f + __expf(-c01.y));
            float r2 = __fdividef(1.0f, 1.0f + __expf(-c2));

            out0 = fmaf(weight, r0, out0);
            out1 = fmaf(weight, r1, out1);
            out2 = fmaf(weight, r2, out2);
            light *= att;

            t = t_new;
            dt_cur = dt_next;
            if (!more) break;
        }
    }
    #undef GEOM
    #undef S01
    #undef S2

    out[3*i+0] = out0 + light * BG;
    out[3*i+1] = out1 + light * BG;
    out[3*i+2] = out2 + light * BG;
}

extern "C" void kernel_launch(void* const* d_in, const int* in_sizes, int n_in,
                              void* d_out, int out_size)
{
    const float* tree      = (const float*)d_in[0];
    const float* origins   = (const float*)d_in[1];
    const float* dirs      = (const float*)d_in[2];
    const float* viewdirs  = (const float*)d_in[3];
    const float* invradius = (const float*)d_in[4];
    float* out = (float*)d_out;

    int nb = in_sizes[1] / 3;

    convert_kernel<<<NVOX / 64, 256>>>(tree);

    int threads = 128;
    int blocks = (nb + threads - 1) / threads;
    volrend_kernel<<<blocks, threads>>>(origins, dirs, viewdirs, invradius, out, nb);
}

// round 15
// speedup vs baseline: 1.8952x; 1.8952x over previous
#include <cuda_runtime.h>
#include <cuda_fp16.h>

#define RR 128
#define BASIS 9
#define DATA_DIM 28
#define NUM_STEPS 256
#define STEP_SIZE 0.001f
#define BG 1.0f

#define NVOX (RR*RR*RR)           // 2097152
// 32 halves per voxel, interleaved for HFMA2 (R6 layout):
//  halves 0..17 : (c0_j, c1_j) pairs, j = 0..8
//  halves 18..26: c2_0 .. c2_8
//  half  27     : 0
//  half  28     : sigma
//  halves 29..31: 0
__device__ __align__(64) uint4 g_grid[NVOX * 4];   // 128 MiB, 64B records

// 256-bit load (Blackwell): one LDG.E.256 pulls 32B per lane.
__device__ __forceinline__ void ldg256(const uint4* p, uint4& a, uint4& b)
{
    asm volatile("ld.global.nc.v8.b32 {%0,%1,%2,%3,%4,%5,%6,%7}, [%8];"
        : "=r"(a.x), "=r"(a.y), "=r"(a.z), "=r"(a.w),
          "=r"(b.x), "=r"(b.y), "=r"(b.z), "=r"(b.w)
        : "l"(p));
}

// ---------------------------------------------------------------------------
// Conversion via smem staging. Source reads are STREAMING (__ldcs) so they
// do not pollute L2: at convert end, L2 holds the freshly-written grid,
// which the render then hits at ~98%.
// ---------------------------------------------------------------------------
__global__ void __launch_bounds__(256)
convert_kernel(const float* __restrict__ tree)
{
    __shared__ float sm[64 * DATA_DIM];
    int tid = threadIdx.x;
    long long v0 = (long long)blockIdx.x * 64;

    const float4* src4 = reinterpret_cast<const float4*>(tree) + v0 * 7;
    float4* sm4 = reinterpret_cast<float4*>(sm);
    #pragma unroll
    for (int k = tid; k < 448; k += 256)
        sm4[k] = __ldcs(src4 + k);          // evict-first: keep L2 for grid
    __syncthreads();

    int vl = tid >> 2;
    int q  = tid & 3;
    const float* f = sm + vl * DATA_DIM;

    __half h[8];
    if (q == 0) {
        h[0]=__float2half_rn(f[0]);  h[1]=__float2half_rn(f[9]);
        h[2]=__float2half_rn(f[1]);  h[3]=__float2half_rn(f[10]);
        h[4]=__float2half_rn(f[2]);  h[5]=__float2half_rn(f[11]);
        h[6]=__float2half_rn(f[3]);  h[7]=__float2half_rn(f[12]);
    } else if (q == 1) {
        h[0]=__float2half_rn(f[4]);  h[1]=__float2half_rn(f[13]);
        h[2]=__float2half_rn(f[5]);  h[3]=__float2half_rn(f[14]);
        h[4]=__float2half_rn(f[6]);  h[5]=__float2half_rn(f[15]);
        h[6]=__float2half_rn(f[7]);  h[7]=__float2half_rn(f[16]);
    } else if (q == 2) {
        h[0]=__float2half_rn(f[8]);  h[1]=__float2half_rn(f[17]);
        h[2]=__float2half_rn(f[18]); h[3]=__float2half_rn(f[19]);
        h[4]=__float2half_rn(f[20]); h[5]=__float2half_rn(f[21]);
        h[6]=__float2half_rn(f[22]); h[7]=__float2half_rn(f[23]);
    } else {
        h[0]=__float2half_rn(f[24]); h[1]=__float2half_rn(f[25]);
        h[2]=__float2half_rn(f[26]); h[3]=__float2half_rn(0.0f);
        h[4]=__float2half_rn(f[27]); h[5]=__float2half_rn(0.0f);
        h[6]=__float2half_rn(0.0f);  h[7]=__float2half_rn(0.0f);
    }
    g_grid[v0 * 4 + tid] = *reinterpret_cast<uint4*>(h);   // write-back: allocates grid in L2
}

// ---------------------------------------------------------------------------
// Main renderer: R12 structure (depth-1 pipeline + LDG.256 + HFMA2 shading)
// ---------------------------------------------------------------------------
__global__ void __launch_bounds__(128, 9)
volrend_kernel(const float* __restrict__ origins,
               const float* __restrict__ dirs,
               const float* __restrict__ viewdirs,
               const float* __restrict__ invradius,
               float* __restrict__ out,
               int nb)
{
    int i = blockIdx.x * blockDim.x + threadIdx.x;
    if (i >= nb) return;

    float ox = origins[3*i+0], oy = origins[3*i+1], oz = origins[3*i+2];
    float dx = dirs[3*i+0],    dy = dirs[3*i+1],    dz = dirs[3*i+2];
    float inv_norm = rsqrtf(dx*dx + dy*dy + dz*dz);
    dx *= inv_norm; dy *= inv_norm; dz *= inv_norm;

    float vx = viewdirs[3*i+0], vy = viewdirs[3*i+1], vz = viewdirs[3*i+2];

    float sh[BASIS];
    sh[0] =  0.28209479177387814f;
    sh[1] = -0.4886025119029199f * vy;
    sh[2] =  0.4886025119029199f * vz;
    sh[3] = -0.4886025119029199f * vx;
    sh[4] =  1.0925484305920792f * vx * vy;
    sh[5] = -1.0925484305920792f * vy * vz;
    sh[6] =  0.31539156525252005f * (2.0f*vz*vz - vx*vx - vy*vy);
    sh[7] = -1.0925484305920792f * vx * vz;
    sh[8] =  0.5462742152960396f * (vx*vx - vy*vy);

    // HFMA2 operand packs
    __half2 s01[BASIS];
    #pragma unroll
    for (int j = 0; j < BASIS; ++j) s01[j] = __floats2half2_rn(sh[j], sh[j]);
    __half2 s2[5];
    s2[0] = __floats2half2_rn(sh[0], sh[1]);
    s2[1] = __floats2half2_rn(sh[2], sh[3]);
    s2[2] = __floats2half2_rn(sh[4], sh[5]);
    s2[3] = __floats2half2_rn(sh[6], sh[7]);
    s2[4] = __floats2half2_rn(sh[8], 0.0f);

    float idrx = 1.0f / (dx + 1e-9f);
    float idry = 1.0f / (dy + 1e-9f);
    float idrz = 1.0f / (dz + 1e-9f);

    float t1x = -ox * idrx, t2x = t1x + idrx;
    float t1y = -oy * idry, t2y = t1y + idry;
    float t1z = -oz * idrz, t2z = t1z + idrz;
    float tmin = fmaxf(fmaxf(fminf(t1x,t2x), fminf(t1y,t2y)), fminf(t1z,t2z));
    tmin = fmaxf(tmin, 0.0f);
    float tmax = fminf(fminf(fmaxf(t1x,t2x), fmaxf(t1y,t2y)), fmaxf(t1z,t2z));
    tmax = fminf(tmax, 1e9f);

    float irx = invradius[0], iry = invradius[1], irz = invradius[2];
    float dsx = dx / irx, dsy = dy / iry, dsz = dz / irz;
    float delta_scale = sqrtf(dsx*dsx + dsy*dsy + dsz*dsz);

    float oxR = ox * (float)RR, oyR = oy * (float)RR, ozR = oz * (float)RR;
    float dxR = dx * (float)RR, dyR = dy * (float)RR, dzR = dz * (float)RR;

    float t = tmin;
    float light = 1.0f;
    float out0 = 0.0f, out1 = 0.0f, out2 = 0.0f;
    const float cube_sz = 1.0f / (float)RR;

    #define GEOM(tt, dt_o, vp_o)                                               \
    {                                                                          \
        float px = fmaf((tt), dxR, oxR);                                       \
        float py = fmaf((tt), dyR, oyR);                                       \
        float pz = fmaf((tt), dzR, ozR);                                       \
        float fx = fminf(fmaxf(floorf(px), 0.0f), (float)(RR-1));              \
        float fy = fminf(fmaxf(floorf(py), 0.0f), (float)(RR-1));              \
        float fz = fminf(fmaxf(floorf(pz), 0.0f), (float)(RR-1));              \
        int flat = (int)fmaf(fx, 16384.0f, fmaf(fy, 128.0f, fz));              \
        (vp_o) = g_grid + (size_t)flat * 4;                                    \
        float cx = px - fx, cy = py - fy, cz = pz - fz;                        \
        float u1x = -cx * idrx, u2x = u1x + idrx;                              \
        float u1y = -cy * idry, u2y = u1y + idry;                              \
        float u1z = -cz * idrz, u2z = u1z + idrz;                              \
        float s0 = fmaxf(fmaxf(fminf(u1x,u2x), fminf(u1y,u2y)), fminf(u1z,u2z)); \
        s0 = fmaxf(s0, 0.0f);                                                  \
        float s1 = fminf(fminf(fmaxf(u1x,u2x), fmaxf(u1y,u2y)), fmaxf(u1z,u2z)); \
        s1 = fminf(s1, 1e9f);                                                  \
        (dt_o) = (s1 - s0) * cube_sz + STEP_SIZE;                              \
    }

    if (tmin < tmax) {
        float dt_cur;
        const uint4* vp;
        GEOM(t, dt_cur, vp);
        uint4 b0, b1, b2, b3;
        ldg256(vp,     b0, b1);
        ldg256(vp + 2, b2, b3);

        #pragma unroll 1
        for (int s = 0; s < NUM_STEPS; ++s) {
            uint4 a0 = b0, a1 = b1, a2 = b2, a3 = b3;
            float dt = dt_cur;

            // Prefetch next step before shading
            float t_new = t + dt;
            bool more = (t_new < tmax) && (s + 1 < NUM_STEPS);
            float dt_next = 0.0f;
            if (more) {
                const uint4* vpn;
                GEOM(t_new, dt_next, vpn);
                ldg256(vpn,     b0, b1);
                ldg256(vpn + 2, b2, b3);
            }

            // Shade: half2 SIMD dot products
            __half2 v[16];
            *reinterpret_cast<uint4*>(v +  0) = a0;
            *reinterpret_cast<uint4*>(v +  4) = a1;
            *reinterpret_cast<uint4*>(v +  8) = a2;
            *reinterpret_cast<uint4*>(v + 12) = a3;

            __half2 acc01 = __hmul2(s01[0], v[0]);
            #pragma unroll
            for (int j = 1; j < BASIS; ++j)
                acc01 = __hfma2(s01[j], v[j], acc01);
            __half2 acc2 = __hmul2(s2[0], v[9]);
            #pragma unroll
            for (int k = 1; k < 5; ++k)
                acc2 = __hfma2(s2[k], v[9 + k], acc2);

            float2 c01 = __half22float2(acc01);
            float2 c2p = __half22float2(acc2);
            float c2 = c2p.x + c2p.y;

            float sigma = fmaxf(__half2float(__low2half(v[14])), 0.0f);
            float att = __expf(-dt * sigma * delta_scale);
            float weight = light * (1.0f - att);

            float r0 = __fdividef(1.0f, 1.0f + __expf(-c01.x));
            float r1 = __fdividef(1.0f, 1.0f + __expf(-c01.y));
            float r2 = __fdividef(1.0f, 1.0f + __expf(-c2));

            out0 = fmaf(weight, r0, out0);
            out1 = fmaf(weight, r1, out1);
            out2 = fmaf(weight, r2, out2);
            light *= att;

            t = t_new;
            dt_cur = dt_next;
            if (!more) break;
        }
    }
    #undef GEOM

    out[3*i+0] = out0 + light * BG;
    out[3*i+1] = out1 + light * BG;
    out[3*i+2] = out2 + light * BG;
}

extern "C" void kernel_launch(void* const* d_in, const int* in_sizes, int n_in,
                              void* d_out, int out_size)
{
    const float* tree      = (const float*)d_in[0];
    const float* origins   = (const float*)d_in[1];
    const float* dirs      = (const float*)d_in[2];
    const float* viewdirs  = (const float*)d_in[3];
    const float* invradius = (const float*)d_in[4];
    float* out = (float*)d_out;

    int nb = in_sizes[1] / 3;

    convert_kernel<<<NVOX / 64, 256>>>(tree);

    int threads = 128;
    int blocks = (nb + threads - 1) / threads;
    volrend_kernel<<<blocks, threads>>>(origins, dirs, viewdirs, invradius, out, nb);
}

// round 16
// speedup vs baseline: 2.9687x; 1.5665x over previous
#include <cuda_runtime.h>
#include <cuda_fp16.h>

#define RR 128
#define BASIS 9
#define DATA_DIM 28
#define NUM_STEPS 256
#define STEP_SIZE 0.001f
#define BG 1.0f

#define NVOX (RR*RR*RR)           // 2097152

// 32 B per voxel (2 uint4), int8 block-quantized:
//  w0 = c0[0..3]  w1 = c0[4..7]
//  w2 = c1[0..3]  w3 = c1[4..7]
//  w4 = c2[0..3]  w5 = c2[4..7]
//  w6 = (c0_8, c1_8, c2_8, 0)
//  w7 = (scale:fp16 low, sigma:fp16 high)
__device__ __align__(32) uint4 g_grid[NVOX * 2];   // 64 MiB

// 256-bit load (Blackwell): one LDG.E.256 pulls 32B per lane.
__device__ __forceinline__ void ldg256(const uint4* p, uint4& a, uint4& b)
{
    asm volatile("ld.global.nc.v8.b32 {%0,%1,%2,%3,%4,%5,%6,%7}, [%8];"
        : "=r"(a.x), "=r"(a.y), "=r"(a.z), "=r"(a.w),
          "=r"(b.x), "=r"(b.y), "=r"(b.z), "=r"(b.w)
        : "l"(p));
}

__device__ __forceinline__ unsigned pack8(int a, int b, int c, int d)
{
    return (unsigned)(a & 0xff) | ((unsigned)(b & 0xff) << 8) |
           ((unsigned)(c & 0xff) << 16) | ((unsigned)(d & 0xff) << 24);
}

// ---------------------------------------------------------------------------
// Conversion: fp32 [NVOX,28] -> int8-quantized 32B records.
// 256 threads stage 256 voxels in smem (coalesced), 1 thread packs 1 voxel.
// ---------------------------------------------------------------------------
__global__ void __launch_bounds__(256)
convert_kernel(const float* __restrict__ tree)
{
    __shared__ float sm[256 * DATA_DIM];   // 28 KiB
    int tid = threadIdx.x;
    long long v0 = (long long)blockIdx.x * 256;

    const float4* src4 = reinterpret_cast<const float4*>(tree) + v0 * 7;
    float4* sm4 = reinterpret_cast<float4*>(sm);
    #pragma unroll
    for (int k = 0; k < 7; ++k)
        sm4[k * 256 + tid] = __ldcs(src4 + k * 256 + tid);
    __syncthreads();

    const float* f = sm + tid * DATA_DIM;
    float amax = 1e-4f;
    #pragma unroll
    for (int j = 0; j < 27; ++j)
        amax = fmaxf(amax, fabsf(f[j]));
    float scale = amax * (1.0f / 127.0f);
    float inv   = 127.0f / amax;

    int q[27];
    #pragma unroll
    for (int j = 0; j < 27; ++j) {
        float t = rintf(f[j] * inv);
        q[j] = (int)t;
    }

    uint4 o0, o1;
    o0.x = pack8(q[0],  q[1],  q[2],  q[3]);
    o0.y = pack8(q[4],  q[5],  q[6],  q[7]);
    o0.z = pack8(q[9],  q[10], q[11], q[12]);
    o0.w = pack8(q[13], q[14], q[15], q[16]);
    o1.x = pack8(q[18], q[19], q[20], q[21]);
    o1.y = pack8(q[22], q[23], q[24], q[25]);
    o1.z = pack8(q[8],  q[17], q[26], 0);
    __half2 sv = __floats2half2_rn(scale, f[27]);   // (scale, sigma)
    o1.w = *reinterpret_cast<unsigned*>(&sv);

    uint4* dst = g_grid + (v0 + tid) * 2;
    dst[0] = o0;
    dst[1] = o1;
}

// ---------------------------------------------------------------------------
// Main renderer: depth-1 pipeline, single LDG.256 per step, dp4a shading.
// ---------------------------------------------------------------------------
__global__ void __launch_bounds__(128, 9)
volrend_kernel(const float* __restrict__ origins,
               const float* __restrict__ dirs,
               const float* __restrict__ viewdirs,
               const float* __restrict__ invradius,
               float* __restrict__ out,
               int nb)
{
    int i = blockIdx.x * blockDim.x + threadIdx.x;
    if (i >= nb) return;

    float ox = origins[3*i+0], oy = origins[3*i+1], oz = origins[3*i+2];
    float dx = dirs[3*i+0],    dy = dirs[3*i+1],    dz = dirs[3*i+2];
    float inv_norm = rsqrtf(dx*dx + dy*dy + dz*dz);
    dx *= inv_norm; dy *= inv_norm; dz *= inv_norm;

    float vx = viewdirs[3*i+0], vy = viewdirs[3*i+1], vz = viewdirs[3*i+2];

    float sh[BASIS];
    sh[0] =  0.28209479177387814f;
    sh[1] = -0.4886025119029199f * vy;
    sh[2] =  0.4886025119029199f * vz;
    sh[3] = -0.4886025119029199f * vx;
    sh[4] =  1.0925484305920792f * vx * vy;
    sh[5] = -1.0925484305920792f * vy * vz;
    sh[6] =  0.31539156525252005f * (2.0f*vz*vz - vx*vx - vy*vy);
    sh[7] = -1.0925484305920792f * vx * vz;
    sh[8] =  0.5462742152960396f * (vx*vx - vy*vy);

    // Per-ray int8 quantized SH vector for dp4a
    float m = 1e-8f;
    #pragma unroll
    for (int j = 0; j < BASIS; ++j) m = fmaxf(m, fabsf(sh[j]));
    float ssh = m * (1.0f / 127.0f);
    float qinv = 127.0f / m;
    int qs[BASIS];
    #pragma unroll
    for (int j = 0; j < BASIS; ++j) qs[j] = (int)rintf(sh[j] * qinv);
    int s03 = (int)pack8(qs[0], qs[1], qs[2], qs[3]);
    int s47 = (int)pack8(qs[4], qs[5], qs[6], qs[7]);
    int e0  = (int)pack8(qs[8], 0, 0, 0);
    int e1  = (int)pack8(0, qs[8], 0, 0);
    int e2  = (int)pack8(0, 0, qs[8], 0);

    float idrx = 1.0f / (dx + 1e-9f);
    float idry = 1.0f / (dy + 1e-9f);
    float idrz = 1.0f / (dz + 1e-9f);

    float t1x = -ox * idrx, t2x = t1x + idrx;
    float t1y = -oy * idry, t2y = t1y + idry;
    float t1z = -oz * idrz, t2z = t1z + idrz;
    float tmin = fmaxf(fmaxf(fminf(t1x,t2x), fminf(t1y,t2y)), fminf(t1z,t2z));
    tmin = fmaxf(tmin, 0.0f);
    float tmax = fminf(fminf(fmaxf(t1x,t2x), fmaxf(t1y,t2y)), fmaxf(t1z,t2z));
    tmax = fminf(tmax, 1e9f);

    float irx = invradius[0], iry = invradius[1], irz = invradius[2];
    float dsx = dx / irx, dsy = dy / iry, dsz = dz / irz;
    float delta_scale = sqrtf(dsx*dsx + dsy*dsy + dsz*dsz);

    float oxR = ox * (float)RR, oyR = oy * (float)RR, ozR = oz * (float)RR;
    float dxR = dx * (float)RR, dyR = dy * (float)RR, dzR = dz * (float)RR;

    float t = tmin;
    float light = 1.0f;
    float out0 = 0.0f, out1 = 0.0f, out2 = 0.0f;
    const float cube_sz = 1.0f / (float)RR;

    #define GEOM(tt, dt_o, vp_o)                                               \
    {                                                                          \
        float px = fmaf((tt), dxR, oxR);                                       \
        float py = fmaf((tt), dyR, oyR);                                       \
        float pz = fmaf((tt), dzR, ozR);                                       \
        float fx = fminf(fmaxf(floorf(px), 0.0f), (float)(RR-1));              \
        float fy = fminf(fmaxf(floorf(py), 0.0f), (float)(RR-1));              \
        float fz = fminf(fmaxf(floorf(pz), 0.0f), (float)(RR-1));              \
        int flat = (int)fmaf(fx, 16384.0f, fmaf(fy, 128.0f, fz));              \
        (vp_o) = g_grid + (size_t)flat * 2;                                    \
        float cx = px - fx, cy = py - fy, cz = pz - fz;                        \
        float u1x = -cx * idrx, u2x = u1x + idrx;                              \
        float u1y = -cy * idry, u2y = u1y + idry;                              \
        float u1z = -cz * idrz, u2z = u1z + idrz;                              \
        float s0 = fmaxf(fmaxf(fminf(u1x,u2x), fminf(u1y,u2y)), fminf(u1z,u2z)); \
        s0 = fmaxf(s0, 0.0f);                                                  \
        float s1 = fminf(fminf(fmaxf(u1x,u2x), fmaxf(u1y,u2y)), fmaxf(u1z,u2z)); \
        s1 = fminf(s1, 1e9f);                                                  \
        (dt_o) = (s1 - s0) * cube_sz + STEP_SIZE;                              \
    }

    if (tmin < tmax) {
        float dt_cur;
        const uint4* vp;
        GEOM(t, dt_cur, vp);
        uint4 b0, b1;
        ldg256(vp, b0, b1);

        #pragma unroll 1
        for (int s = 0; s < NUM_STEPS; ++s) {
            uint4 a0 = b0, a1 = b1;
            float dt = dt_cur;

            // Prefetch next step before shading
            float t_new = t + dt;
            bool more = (t_new < tmax) && (s + 1 < NUM_STEPS);
            float dt_next = 0.0f;
            if (more) {
                const uint4* vpn;
                GEOM(t_new, dt_next, vpn);
                ldg256(vpn, b0, b1);
            }

            // Shade: int8 dp4a dot products
            int i0 = __dp4a((int)a0.x, s03, __dp4a((int)a0.y, s47,
                      __dp4a((int)a1.z, e0, 0)));
            int i1 = __dp4a((int)a0.z, s03, __dp4a((int)a0.w, s47,
                      __dp4a((int)a1.z, e1, 0)));
            int i2 = __dp4a((int)a1.x, s03, __dp4a((int)a1.y, s47,
                      __dp4a((int)a1.z, e2, 0)));

            __half2 sv = *reinterpret_cast<__half2*>(&a1.w);
            float2 svf = __half22float2(sv);       // (scale_vox, sigma)
            float cs = svf.x * ssh;
            float sigma = fmaxf(svf.y, 0.0f);

            float c0 = (float)i0 * cs;
            float c1 = (float)i1 * cs;
            float c2 = (float)i2 * cs;

            float att = __expf(-dt * sigma * delta_scale);
            float weight = light * (1.0f - att);

            float r0 = __fdividef(1.0f, 1.0f + __expf(-c0));
            float r1 = __fdividef(1.0f, 1.0f + __expf(-c1));
            float r2 = __fdividef(1.0f, 1.0f + __expf(-c2));

            out0 = fmaf(weight, r0, out0);
            out1 = fmaf(weight, r1, out1);
            out2 = fmaf(weight, r2, out2);
            light *= att;

            t = t_new;
            dt_cur = dt_next;
            if (!more) break;
        }
    }
    #undef GEOM

    out[3*i+0] = out0 + light * BG;
    out[3*i+1] = out1 + light * BG;
    out[3*i+2] = out2 + light * BG;
}

extern "C" void kernel_launch(void* const* d_in, const int* in_sizes, int n_in,
                              void* d_out, int out_size)
{
    const float* tree      = (const float*)d_in[0];
    const float* origins   = (const float*)d_in[1];
    const float* dirs      = (const float*)d_in[2];
    const float* viewdirs  = (const float*)d_in[3];
    const float* invradius = (const float*)d_in[4];
    float* out = (float*)d_out;

    int nb = in_sizes[1] / 3;

    convert_kernel<<<NVOX / 256, 256>>>(tree);

    int threads = 128;
    int blocks = (nb + threads - 1) / threads;
    volrend_kernel<<<blocks, threads>>>(origins, dirs, viewdirs, invradius, out, nb);
}

// round 17
// speedup vs baseline: 3.1039x; 1.0455x over previous
#include <cuda_runtime.h>
#include <cuda_fp16.h>

#define RR 128
#define BASIS 9
#define DATA_DIM 28
#define NUM_STEPS 256
#define STEP_SIZE 0.001f
#define BG 1.0f

#define NVOX (RR*RR*RR)           // 2097152

// 32 B per voxel (2 uint4), int8 block-quantized:
//  w0 = c0[0..3]  w1 = c0[4..7]
//  w2 = c1[0..3]  w3 = c1[4..7]
//  w4 = c2[0..3]  w5 = c2[4..7]
//  w6 = (c0_8, c1_8, c2_8, 0)
//  w7 = (scale:fp16 low, sigma:fp16 high)
__device__ __align__(32) uint4 g_grid[NVOX * 2];   // 64 MiB

// 256-bit load (Blackwell): one LDG.E.256 pulls 32B per lane.
__device__ __forceinline__ void ldg256(const uint4* p, uint4& a, uint4& b)
{
    asm volatile("ld.global.nc.v8.b32 {%0,%1,%2,%3,%4,%5,%6,%7}, [%8];"
        : "=r"(a.x), "=r"(a.y), "=r"(a.z), "=r"(a.w),
          "=r"(b.x), "=r"(b.y), "=r"(b.z), "=r"(b.w)
        : "l"(p));
}

__device__ __forceinline__ unsigned pack8(int a, int b, int c, int d)
{
    return (unsigned)(a & 0xff) | ((unsigned)(b & 0xff) << 8) |
           ((unsigned)(c & 0xff) << 16) | ((unsigned)(d & 0xff) << 24);
}

// ---------------------------------------------------------------------------
// Conversion: fp32 [NVOX,28] -> int8-quantized 32B records. (R16 version)
// ---------------------------------------------------------------------------
__global__ void __launch_bounds__(256)
convert_kernel(const float* __restrict__ tree)
{
    __shared__ float sm[256 * DATA_DIM];   // 28 KiB
    int tid = threadIdx.x;
    long long v0 = (long long)blockIdx.x * 256;

    const float4* src4 = reinterpret_cast<const float4*>(tree) + v0 * 7;
    float4* sm4 = reinterpret_cast<float4*>(sm);
    #pragma unroll
    for (int k = 0; k < 7; ++k)
        sm4[k * 256 + tid] = __ldcs(src4 + k * 256 + tid);
    __syncthreads();

    const float* f = sm + tid * DATA_DIM;
    float amax = 1e-4f;
    #pragma unroll
    for (int j = 0; j < 27; ++j)
        amax = fmaxf(amax, fabsf(f[j]));
    float scale = amax * (1.0f / 127.0f);
    float inv   = 127.0f / amax;

    int q[27];
    #pragma unroll
    for (int j = 0; j < 27; ++j)
        q[j] = (int)rintf(f[j] * inv);

    uint4 o0, o1;
    o0.x = pack8(q[0],  q[1],  q[2],  q[3]);
    o0.y = pack8(q[4],  q[5],  q[6],  q[7]);
    o0.z = pack8(q[9],  q[10], q[11], q[12]);
    o0.w = pack8(q[13], q[14], q[15], q[16]);
    o1.x = pack8(q[18], q[19], q[20], q[21]);
    o1.y = pack8(q[22], q[23], q[24], q[25]);
    o1.z = pack8(q[8],  q[17], q[26], 0);
    __half2 sv = __floats2half2_rn(scale, f[27]);   // (scale, sigma)
    o1.w = *reinterpret_cast<unsigned*>(&sv);

    uint4* dst = g_grid + (v0 + tid) * 2;
    dst[0] = o0;
    dst[1] = o1;
}

// ---------------------------------------------------------------------------
// Main renderer: depth-1 pipeline, 1×LDG.256/step, dp4a shading, slim GEOM.
// ---------------------------------------------------------------------------
__global__ void __launch_bounds__(128, 9)
volrend_kernel(const float* __restrict__ origins,
               const float* __restrict__ dirs,
               const float* __restrict__ viewdirs,
               const float* __restrict__ invradius,
               float* __restrict__ out,
               int nb)
{
    int i = blockIdx.x * blockDim.x + threadIdx.x;
    if (i >= nb) return;

    float ox = origins[3*i+0], oy = origins[3*i+1], oz = origins[3*i+2];
    float dx = dirs[3*i+0],    dy = dirs[3*i+1],    dz = dirs[3*i+2];
    float inv_norm = rsqrtf(dx*dx + dy*dy + dz*dz);
    dx *= inv_norm; dy *= inv_norm; dz *= inv_norm;

    float vx = viewdirs[3*i+0], vy = viewdirs[3*i+1], vz = viewdirs[3*i+2];

    float sh[BASIS];
    sh[0] =  0.28209479177387814f;
    sh[1] = -0.4886025119029199f * vy;
    sh[2] =  0.4886025119029199f * vz;
    sh[3] = -0.4886025119029199f * vx;
    sh[4] =  1.0925484305920792f * vx * vy;
    sh[5] = -1.0925484305920792f * vy * vz;
    sh[6] =  0.31539156525252005f * (2.0f*vz*vz - vx*vx - vy*vy);
    sh[7] = -1.0925484305920792f * vx * vz;
    sh[8] =  0.5462742152960396f * (vx*vx - vy*vy);

    // Per-ray int8 quantized SH vector for dp4a
    float m = 1e-8f;
    #pragma unroll
    for (int j = 0; j < BASIS; ++j) m = fmaxf(m, fabsf(sh[j]));
    float ssh = m * (1.0f / 127.0f);
    float qinv = 127.0f / m;
    int qs[BASIS];
    #pragma unroll
    for (int j = 0; j < BASIS; ++j) qs[j] = (int)rintf(sh[j] * qinv);
    int s03 = (int)pack8(qs[0], qs[1], qs[2], qs[3]);
    int s47 = (int)pack8(qs[4], qs[5], qs[6], qs[7]);
    int e0  = (int)pack8(qs[8], 0, 0, 0);
    int e1  = (int)pack8(0, qs[8], 0, 0);
    int e2  = (int)pack8(0, 0, qs[8], 0);

    float idrx = 1.0f / (dx + 1e-9f);
    float idry = 1.0f / (dy + 1e-9f);
    float idrz = 1.0f / (dz + 1e-9f);

    float t1x = -ox * idrx, t2x = t1x + idrx;
    float t1y = -oy * idry, t2y = t1y + idry;
    float t1z = -oz * idrz, t2z = t1z + idrz;
    float tmin = fmaxf(fmaxf(fminf(t1x,t2x), fminf(t1y,t2y)), fminf(t1z,t2z));
    tmin = fmaxf(tmin, 0.0f);
    float tmax = fminf(fminf(fmaxf(t1x,t2x), fmaxf(t1y,t2y)), fmaxf(t1z,t2z));
    tmax = fminf(tmax, 1e9f);

    float irx = invradius[0], iry = invradius[1], irz = invradius[2];
    float dsx = dx / irx, dsy = dy / iry, dsz = dz / irz;
    float delta_scale = sqrtf(dsx*dsx + dsy*dsy + dsz*dsz);

    float oxR = ox * (float)RR, oyR = oy * (float)RR, ozR = oz * (float)RR;
    float dxR = dx * (float)RR, dyR = dy * (float)RR, dzR = dz * (float)RR;

    // Pre-scaled inverse dirs for the slim cell-exit computation:
    // dt = min3( fmaf(-cx, idrc, bc) ) + STEP_SIZE
    const float cube_sz = 1.0f / (float)RR;
    float idcx = idrx * cube_sz, idcy = idry * cube_sz, idcz = idrz * cube_sz;
    float bcx = fmaxf(idcx, 0.0f), bcy = fmaxf(idcy, 0.0f), bcz = fmaxf(idcz, 0.0f);

    float t = tmin;
    float light = 1.0f;
    float out0 = 0.0f, out1 = 0.0f, out2 = 0.0f;

    #define GEOM(tt, dt_o, vp_o)                                               \
    {                                                                          \
        float px = fmaf((tt), dxR, oxR);                                       \
        float py = fmaf((tt), dyR, oyR);                                       \
        float pz = fmaf((tt), dzR, ozR);                                       \
        float fx = fminf(fmaxf(floorf(px), 0.0f), (float)(RR-1));              \
        float fy = fminf(fmaxf(floorf(py), 0.0f), (float)(RR-1));              \
        float fz = fminf(fmaxf(floorf(pz), 0.0f), (float)(RR-1));              \
        int flat = (int)fmaf(fx, 16384.0f, fmaf(fy, 128.0f, fz));              \
        (vp_o) = g_grid + (size_t)flat * 2;                                    \
        float ex = fmaf(fx - px, idcx, bcx);                                   \
        float ey = fmaf(fy - py, idcy, bcy);                                   \
        float ez = fmaf(fz - pz, idcz, bcz);                                   \
        (dt_o) = fminf(fminf(ex, ey), ez) + STEP_SIZE;                         \
    }

    if (tmin < tmax) {
        float dt_cur;
        const uint4* vp;
        GEOM(t, dt_cur, vp);
        uint4 b0, b1;
        ldg256(vp, b0, b1);

        #pragma unroll 1
        for (int s = 0; s < NUM_STEPS; ++s) {
            uint4 a0 = b0, a1 = b1;
            float dt = dt_cur;

            // Prefetch next step before shading
            float t_new = t + dt;
            bool more = (t_new < tmax) && (s + 1 < NUM_STEPS);
            float dt_next = 0.0f;
            if (more) {
                const uint4* vpn;
                GEOM(t_new, dt_next, vpn);
                ldg256(vpn, b0, b1);
            }

            // Shade: int8 dp4a dot products
            int i0 = __dp4a((int)a0.x, s03, __dp4a((int)a0.y, s47,
                      __dp4a((int)a1.z, e0, 0)));
            int i1 = __dp4a((int)a0.z, s03, __dp4a((int)a0.w, s47,
                      __dp4a((int)a1.z, e1, 0)));
            int i2 = __dp4a((int)a1.x, s03, __dp4a((int)a1.y, s47,
                      __dp4a((int)a1.z, e2, 0)));

            __half2 sv = *reinterpret_cast<__half2*>(&a1.w);
            float2 svf = __half22float2(sv);       // (scale_vox, sigma)
            float cs = svf.x * ssh;
            float sigma = fmaxf(svf.y, 0.0f);

            float c0 = (float)i0 * cs;
            float c1 = (float)i1 * cs;
            float c2 = (float)i2 * cs;

            float att = __expf(-dt * sigma * delta_scale);
            float weight = light * (1.0f - att);

            float r0 = __fdividef(1.0f, 1.0f + __expf(-c0));
            float r1 = __fdividef(1.0f, 1.0f + __expf(-c1));
            float r2 = __fdividef(1.0f, 1.0f + __expf(-c2));

            out0 = fmaf(weight, r0, out0);
            out1 = fmaf(weight, r1, out1);
            out2 = fmaf(weight, r2, out2);
            light *= att;

            t = t_new;
            dt_cur = dt_next;
            if (!more) break;
        }
    }
    #undef GEOM

    out[3*i+0] = out0 + light * BG;
    out[3*i+1] = out1 + light * BG;
    out[3*i+2] = out2 + light * BG;
}

extern "C" void kernel_launch(void* const* d_in, const int* in_sizes, int n_in,
                              void* d_out, int out_size)
{
    const float* tree      = (const float*)d_in[0];
    const float* origins   = (const float*)d_in[1];
    const float* dirs      = (const float*)d_in[2];
    const float* viewdirs  = (const float*)d_in[3];
    const float* invradius = (const float*)d_in[4];
    float* out = (float*)d_out;

    int nb = in_sizes[1] / 3;

    convert_kernel<<<NVOX / 256, 256>>>(tree);

    int threads = 128;
    int blocks = (nb + threads - 1) / threads;
    volrend_kernel<<<blocks, threads>>>(origins, dirs, viewdirs, invradius, out, nb);
}